// round 10
// baseline (speedup 1.0000x reference)
#include <cuda_runtime.h>
#include <cuda_bf16.h>
#include <math.h>

#define B 8
#define S 2048
#define D 2048
#define E 8
#define EPS 1e-5f

#define D4 (D / 4)              // 512 float4 per row
#define UROWS 8                 // rows per work unit
#define NUNIT (S / UROWS)       // 256 units per batch
#define CPB 37                  // CTAs per batch
#define NBLK (CPB * B)          // 296 CTAs (2 per SM, single wave)
#define CNTPAD 32               // pad unit counters to one 128B line each

__device__ float g_acc[B * E + B];       // dot[b*E+e], xsum[b] at 64+b
__device__ float g_stats[2 * E];         // [mean, scale] per expert
__device__ unsigned int g_unit[B * CNTPAD];  // per-batch ticket counters
__device__ unsigned int g_ticket;

__global__ void __launch_bounds__(256) router_kernel(
    const float4* __restrict__ x4,
    const float4* __restrict__ W4,
    const float*  __restrict__ gain,
    const float*  __restrict__ init_std,
    const float*  __restrict__ noise,
    const int*    __restrict__ topk_p,
    float* __restrict__ out, int out_size)
{
    const int tid  = threadIdx.x;
    const int warp = tid >> 5, lane = tid & 31;
    const int bid  = blockIdx.x;
    const int b    = bid & 7;                // batch for this CTA

    __shared__ unsigned int s_u;
    __shared__ float s_red[9][8];

    // ---- first ticket ----
    if (tid == 0) s_u = atomicAdd(&g_unit[b * CNTPAD], 1u);
    __syncthreads();
    unsigned int u = s_u;

    const float4* xb = x4 + (size_t)b * S * D4;
    float4 acc0 = make_float4(0.f, 0.f, 0.f, 0.f);   // d4 slot tid
    float4 acc1 = make_float4(0.f, 0.f, 0.f, 0.f);   // d4 slot tid+256

    while (u < NUNIT) {
        __syncthreads();                              // everyone has copied s_u
        if (tid == 0) s_u = atomicAdd(&g_unit[b * CNTPAD], 1u);  // prefetch next

        const float4* p = xb + (size_t)(u * UROWS) * D4;
        // 16 independent LDG.128s, front-batched for MLP
        float4 r0[UROWS], r1[UROWS];
#pragma unroll
        for (int r = 0; r < UROWS; r++) {
            r0[r] = p[(size_t)r * D4 + tid];
            r1[r] = p[(size_t)r * D4 + tid + 256];
        }
#pragma unroll
        for (int r = 0; r < UROWS; r++) {
            acc0.x += r0[r].x; acc0.y += r0[r].y; acc0.z += r0[r].z; acc0.w += r0[r].w;
            acc1.x += r1[r].x; acc1.y += r1[r].y; acc1.z += r1[r].z; acc1.w += r1[r].w;
        }

        __syncthreads();                              // s_u (next ticket) visible
        u = s_u;
    }

    // ---- flush: contract accumulated column sums against W ----
    float v9[9];
#pragma unroll
    for (int e = 0; e < E; e++) {
        float4 w0 = W4[e * D4 + tid];
        float4 w1 = W4[e * D4 + tid + 256];
        v9[e] = acc0.x * w0.x + acc0.y * w0.y + acc0.z * w0.z + acc0.w * w0.w
              + acc1.x * w1.x + acc1.y * w1.y + acc1.z * w1.z + acc1.w * w1.w;
    }
    v9[8] = acc0.x + acc0.y + acc0.z + acc0.w
          + acc1.x + acc1.y + acc1.z + acc1.w;

#pragma unroll
    for (int o = 16; o; o >>= 1)
#pragma unroll
        for (int i = 0; i < 9; i++)
            v9[i] += __shfl_xor_sync(0xFFFFFFFFu, v9[i], o);
    if (lane == 0)
#pragma unroll
        for (int i = 0; i < 9; i++) s_red[i][warp] = v9[i];
    __syncthreads();
    if (tid < 9) {
        float s = 0.f;
#pragma unroll
        for (int w = 0; w < 8; w++) s += s_red[tid][w];
        atomicAdd(&g_acc[tid < 9 - 1 ? b * E + tid : 64 + b], s);
    }

    // ---- first 8 CTAs: per-expert W stats (L2-hot) ----
    if (bid < E) {
        const int e = bid;
        float4 w0 = W4[e * D4 + tid];
        float4 w1 = W4[e * D4 + tid + 256];
        float s  = w0.x + w0.y + w0.z + w0.w + w1.x + w1.y + w1.z + w1.w;
        float ss = w0.x * w0.x + w0.y * w0.y + w0.z * w0.z + w0.w * w0.w
                 + w1.x * w1.x + w1.y * w1.y + w1.z * w1.z + w1.w * w1.w;
#pragma unroll
        for (int o = 16; o; o >>= 1) {
            s  += __shfl_xor_sync(0xFFFFFFFFu, s,  o);
            ss += __shfl_xor_sync(0xFFFFFFFFu, ss, o);
        }
        __shared__ float s_s[8], s_ss[8];
        if (lane == 0) { s_s[warp] = s; s_ss[warp] = ss; }
        __syncthreads();
        if (tid == 0) {
            float ts = 0.f, tss = 0.f;
#pragma unroll
            for (int w = 0; w < 8; w++) { ts += s_s[w]; tss += s_ss[w]; }
            float mean = ts / (float)D;
            float var  = (tss - (float)D * mean * mean) / (float)(D - 1);
            float std  = sqrtf(fmaxf(var, 0.f)) + EPS;
            g_stats[2 * e]     = mean;
            g_stats[2 * e + 1] = init_std[e] / std * gain[e];
        }
    }

    // ---- last-block ticket ----
    __syncthreads();
    __shared__ bool is_last;
    if (tid == 0) {
        __threadfence();
        unsigned t = atomicAdd(&g_ticket, 1u);
        is_last = (t == NBLK - 1);
    }
    __syncthreads();
    if (!is_last) return;

    // ================= finalize (tiny) =================
    __shared__ float s_dot[B * E], s_xsum[B], s_scale[E], s_mean[E];
    if (tid < B * E) s_dot[tid]  = __ldcg(&g_acc[tid]);
    if (tid < B)     s_xsum[tid] = __ldcg(&g_acc[64 + tid]);
    if (tid < E) {
        s_mean[tid]  = __ldcg(&g_stats[2 * tid]);
        s_scale[tid] = __ldcg(&g_stats[2 * tid + 1]);
    }
    __syncthreads();

    if (tid < B) {
        const int bb = tid;
        int k = *topk_p;
        if (k > E) k = E;
        const float invS = 1.0f / (float)S;
        float sc[E];
        float mx = -INFINITY;
#pragma unroll
        for (int e = 0; e < E; e++) {
            float v = s_scale[e] * (s_dot[bb * E + e] - s_mean[e] * s_xsum[bb]) * invS
                      + noise[bb * E + e];
            sc[e] = v;
            mx = fmaxf(mx, v);
        }
        float denom = 0.f;
#pragma unroll
        for (int e = 0; e < E; e++) { sc[e] = expf(sc[e] - mx); denom += sc[e]; }
        float inv = 1.0f / denom;
#pragma unroll
        for (int e = 0; e < E; e++) sc[e] *= inv;

        float comb[E];
        bool taken[E];
#pragma unroll
        for (int e = 0; e < E; e++) { comb[e] = 0.f; taken[e] = false; }

        for (int kk = 0; kk < k; kk++) {
            int best = -1; float bv = -INFINITY;
            for (int e = 0; e < E; e++)
                if (!taken[e] && sc[e] > bv) { bv = sc[e]; best = e; }
            taken[best] = true;
            comb[best] = bv;
            int idx_off = B * E + bb * k + kk;
            int scr_off = B * E + B * k + bb * k + kk;
            if (idx_off < out_size) out[idx_off] = (float)best;
            if (scr_off < out_size) out[scr_off] = bv;
        }
#pragma unroll
        for (int e = 0; e < E; e++) {
            int o = bb * E + e;
            if (o < out_size) out[o] = comb[e];
        }
    }
    __syncthreads();

    // reset all scratch for next graph replay
    if (tid < B * E + B) g_acc[tid] = 0.f;
    if (tid < B) g_unit[tid * CNTPAD] = 0u;
    if (tid == 0) g_ticket = 0u;
}

extern "C" void kernel_launch(void* const* d_in, const int* in_sizes, int n_in,
                              void* d_out, int out_size) {
    const float* x        = (const float*)d_in[0];
    const float* W        = (const float*)d_in[1];
    const float* gain     = (const float*)d_in[2];
    const float* init_std = (const float*)d_in[3];
    const float* noise    = (const float*)d_in[4];
    const int*   topk     = (const int*)d_in[5];
    float* out = (float*)d_out;

    router_kernel<<<NBLK, 256>>>((const float4*)x, (const float4*)W,
                                 gain, init_std, noise, topk, out, out_size);
}